// round 8
// baseline (speedup 1.0000x reference)
#include <cuda_runtime.h>

// EnergyGatedDeltaModel — GB300 sm_103a
// R7 = R6 arithmetic (bit-identical scan: NEON VF4xIC4 dots, fmaf updates,
// certified fast gate |dE|>=1, exact NEON-ordered 1024-chain slow path) with
// two pure-scheduling changes:
//  - scan: 2 batches per warp (256 CTAs) -> two independent dependency chains
//    interleave and hide each other's latency (1 warp/SMSP means nothing else can).
//  - precompute: 64 blocks x 64 threads (phase-parallel, same chains per (v,j)/(v,i)).

#define B_ 512
#define L_ 2048
#define H_ 32
#define V_ 64
#define STEPS (L_ - 1)
#define THRESH 1.0f

__device__ float g_table[V_ * H_];
__device__ float g_ksq[V_];
__device__ float g_denom[V_];
__device__ int   g_writes;

// NEON VF4xIC4 reduction of 32 products (fma-chained accumulators) — R6-identical.
__device__ __forceinline__ float neon_dot32(const float* x, const float* y) {
    float A[16];
#pragma unroll
    for (int c = 0; c < 16; c++) A[c] = __fmul_rn(x[c], y[c]);
#pragma unroll
    for (int c = 0; c < 16; c++) A[c] = fmaf(x[16 + c], y[16 + c], A[c]);
    float V[4];
#pragma unroll
    for (int l = 0; l < 4; l++)
        V[l] = __fadd_rn(__fadd_rn(__fadd_rn(A[l], A[4 + l]), A[8 + l]), A[12 + l]);
    return __fadd_rn(__fadd_rn(V[0], V[2]), __fadd_rn(V[1], V[3]));
}

__device__ __forceinline__ float neon_sum32(const float* t) {
    float A[16];
#pragma unroll
    for (int c = 0; c < 16; c++) A[c] = __fadd_rn(t[c], t[16 + c]);
    float V[4];
#pragma unroll
    for (int l = 0; l < 4; l++)
        V[l] = __fadd_rn(__fadd_rn(__fadd_rn(A[l], A[4 + l]), A[8 + l]), A[12 + l]);
    return __fadd_rn(__fadd_rn(V[0], V[2]), __fadd_rn(V[1], V[3]));
}

// ---------------------------------------------------------------------------
// Precompute: one block per vocab id; same chains as R6, phase-parallel.
// ---------------------------------------------------------------------------
__global__ void precompute_kernel(const float* __restrict__ embed,
                                  const float* __restrict__ w1,
                                  const float* __restrict__ b1,
                                  const float* __restrict__ w2,
                                  const float* __restrict__ b2,
                                  const float* __restrict__ ln_g,
                                  const float* __restrict__ ln_b)
{
    __shared__ float h_sh[H_];
    __shared__ float s_sh[2 * H_];
    __shared__ float x_sh[H_];

    const int v = blockIdx.x;
    const int t = threadIdx.x;
    if (v == 0 && t == 0) g_writes = 0;

    if (t < H_) h_sh[t] = embed[v * H_ + t];
    __syncthreads();

    // phase 1: s_j = relu( (Eigen seq fma chain over i) + b1[j] )
    {
        const int j = t;   // 0..63
        float s = 0.0f;
#pragma unroll
        for (int i = 0; i < H_; i++) s = fmaf(h_sh[i], w1[i * 2 * H_ + j], s);
        s = __fadd_rn(s, b1[j]);
        s_sh[j] = fmaxf(s, 0.0f);
    }
    __syncthreads();

    // phase 2: acc_i = seq fma chain over j; x_i = h + (acc + b2)
    if (t < H_) {
        const int i = t;
        float acc = 0.0f;
#pragma unroll
        for (int j = 0; j < 2 * H_; j++) acc = fmaf(s_sh[j], w2[j * H_ + i], acc);
        float ff = __fadd_rn(acc, b2[i]);
        x_sh[i] = __fadd_rn(h_sh[i], ff);
    }
    __syncthreads();

    // phase 3: LayerNorm + ksq, single thread, R6-identical op order
    if (t == 0) {
        float x[H_], d[H_], sq[H_];
#pragma unroll
        for (int i = 0; i < H_; i++) x[i] = x_sh[i];
        float mu = __fmul_rn(neon_sum32(x), 1.0f / H_);
#pragma unroll
        for (int i = 0; i < H_; i++) {
            d[i] = __fsub_rn(x[i], mu);
            sq[i] = __fmul_rn(d[i], d[i]);
        }
        float var = __fmul_rn(neon_sum32(sq), 1.0f / H_);
        float rs = __fdiv_rn(1.0f, __fsqrt_rn(__fadd_rn(var, 1e-5f)));
        float y[H_];
#pragma unroll
        for (int i = 0; i < H_; i++) {
            y[i] = __fadd_rn(__fmul_rn(__fmul_rn(d[i], rs), ln_g[i]), ln_b[i]);
            g_table[v * H_ + i] = y[i];
            sq[i] = __fmul_rn(y[i], y[i]);
        }
        float ksq = neon_sum32(sq);
        g_ksq[v]   = ksq;
        g_denom[v] = __fadd_rn(ksq, 1e-6f);
    }
}

// ---------------------------------------------------------------------------
// Scan: one warp handles TWO batches (b, b+256) with interleaved chains.
// All per-batch arithmetic bit-identical to R6.
// ---------------------------------------------------------------------------

// Exact slow-path gate: NEON-ordered 1024-sums of M^2 and Mn^2. Mn recomputed
// as fmaf(u, kv, M) (identical values to the fast-path update).
__device__ __forceinline__ int exact_gate(const float* M, float u, const float* kv,
                                          float* Msh, float* Mnsh, int lane,
                                          unsigned FULL)
{
    {
        float4* mr  = (float4*)(Msh  + lane * H_);
        float4* mnr = (float4*)(Mnsh + lane * H_);
#pragma unroll
        for (int q = 0; q < 8; q++) {
            float m0 = M[4*q],   m1 = M[4*q+1], m2 = M[4*q+2], m3 = M[4*q+3];
            mr[q]  = make_float4(m0, m1, m2, m3);
            mnr[q] = make_float4(fmaf(u, kv[4*q],   m0), fmaf(u, kv[4*q+1], m1),
                                 fmaf(u, kv[4*q+2], m2), fmaf(u, kv[4*q+3], m3));
        }
    }
    __syncwarp();
    const float* P = (lane < 16) ? Msh : Mnsh;
    const int c = lane & 15;
    float a = 0.0f;
#pragma unroll
    for (int m = 0; m < 64; m++) {
        float s = P[16 * m + c];
        a = fmaf(s, s, a);
    }
    __syncwarp();
    float Vo[4], Vn[4];
#pragma unroll
    for (int l = 0; l < 4; l++) {
        float a0 = __shfl_sync(FULL, a, l);
        float a1 = __shfl_sync(FULL, a, l + 4);
        float a2 = __shfl_sync(FULL, a, l + 8);
        float a3 = __shfl_sync(FULL, a, l + 12);
        Vo[l] = __fadd_rn(__fadd_rn(__fadd_rn(a0, a1), a2), a3);
        float c0 = __shfl_sync(FULL, a, 16 + l);
        float c1 = __shfl_sync(FULL, a, 20 + l);
        float c2 = __shfl_sync(FULL, a, 24 + l);
        float c3 = __shfl_sync(FULL, a, 28 + l);
        Vn[l] = __fadd_rn(__fadd_rn(__fadd_rn(c0, c1), c2), c3);
    }
    const float eo = __fadd_rn(__fadd_rn(Vo[0], Vo[2]), __fadd_rn(Vo[1], Vo[3]));
    const float en = __fadd_rn(__fadd_rn(Vn[0], Vn[2]), __fadd_rn(Vn[1], Vn[3]));
    return en > eo;
}

__global__ void __launch_bounds__(32) scan_kernel(const int* __restrict__ seq,
                                                  const float* __restrict__ w_read,
                                                  const float* __restrict__ b_read,
                                                  const float* __restrict__ w_out,
                                                  const float* __restrict__ b_out,
                                                  float* __restrict__ out)
{
    __shared__ __align__(16) float tsh[V_ * H_];
    __shared__ __align__(16) float Msh[H_ * H_];
    __shared__ __align__(16) float Mnsh[H_ * H_];
    __shared__ float dnsh[V_];
    __shared__ float kssh[V_];
    __shared__ int   toksA[32];
    __shared__ int   toksB[32];
    __shared__ float scratch[H_];

    const int lane = threadIdx.x;
    const int bA   = blockIdx.x;          // batch A
    const int bB   = blockIdx.x + 256;    // batch B
    const unsigned FULL = 0xffffffffu;

    for (int i = lane; i < V_ * H_; i += 32) tsh[i] = g_table[i];
    dnsh[lane]      = g_denom[lane];
    dnsh[lane + 32] = g_denom[lane + 32];
    kssh[lane]      = g_ksq[lane];
    kssh[lane + 32] = g_ksq[lane + 32];
    __syncwarp();

    float MA[H_], MB[H_];
#pragma unroll
    for (int j = 0; j < H_; j++) { MA[j] = 0.0f; MB[j] = 0.0f; }

    int writes = 0;
    const int* sA = seq + bA * L_;
    const int* sB = seq + bB * L_;

    for (int t0 = 0; t0 < STEPS; t0 += 32) {
        toksA[lane] = sA[t0 + lane];
        toksB[lane] = sB[t0 + lane];
        __syncwarp();
        const int tend = (STEPS - t0) < 32 ? (STEPS - t0) : 32;

        for (int tt = 0; tt < tend; tt++) {
            const int tokA = toksA[tt];
            const int tokB = toksB[tt];

            float kvA[H_], kvB[H_];
            {
                const float4* kpA = (const float4*)(tsh + tokA * H_);
                const float4* kpB = (const float4*)(tsh + tokB * H_);
#pragma unroll
                for (int q = 0; q < 8; q++) {
                    float4 fA = kpA[q];
                    kvA[4*q+0] = fA.x; kvA[4*q+1] = fA.y; kvA[4*q+2] = fA.z; kvA[4*q+3] = fA.w;
                    float4 fB = kpB[q];
                    kvB[4*q+0] = fB.x; kvB[4*q+1] = fB.y; kvB[4*q+2] = fB.z; kvB[4*q+3] = fB.w;
                }
            }
            const float kiA = tsh[tokA * H_ + lane];
            const float kiB = tsh[tokB * H_ + lane];

            // NEON dots (independent chains -> interleaved by scheduler)
            const float vA = neon_dot32(MA, kvA);
            const float vB = neon_dot32(MB, kvB);

            const float uA = __fsub_rn(kiA, __fdiv_rn(vA, dnsh[tokA]));
            const float uB = __fsub_rn(kiB, __fdiv_rn(vB, dnsh[tokB]));

            // 4 interleaved butterflies
            float suvA = __fmul_rn(uA, vA);
            float suuA = __fmul_rn(uA, uA);
            float suvB = __fmul_rn(uB, vB);
            float suuB = __fmul_rn(uB, uB);
#pragma unroll
            for (int o = 16; o > 0; o >>= 1) {
                suvA += __shfl_xor_sync(FULL, suvA, o);
                suuA += __shfl_xor_sync(FULL, suuA, o);
                suvB += __shfl_xor_sync(FULL, suvB, o);
                suuB += __shfl_xor_sync(FULL, suuB, o);
            }
            const float dEA = __fadd_rn(__fadd_rn(suvA, suvA), __fmul_rn(suuA, kssh[tokA]));
            const float dEB = __fadd_rn(__fadd_rn(suvB, suvB), __fmul_rn(suuB, kssh[tokB]));

            int gateA, gateB;
            if (fabsf(dEA) >= THRESH) gateA = dEA > 0.0f;
            else gateA = exact_gate(MA, uA, kvA, Msh, Mnsh, lane, FULL);
            if (fabsf(dEB) >= THRESH) gateB = dEB > 0.0f;
            else gateB = exact_gate(MB, uB, kvB, Msh, Mnsh, lane, FULL);

            if (gateA) {
                writes++;
#pragma unroll
                for (int j = 0; j < H_; j++) MA[j] = fmaf(uA, kvA[j], MA[j]);
            }
            if (gateB) {
                writes++;
#pragma unroll
                for (int j = 0; j < H_; j++) MB[j] = fmaf(uB, kvB[j], MB[j]);
            }
        }
        __syncwarp();
    }

    // -------- readout (both batches), R6-identical arithmetic --------
#pragma unroll
    for (int pass = 0; pass < 2; pass++) {
        const int b = pass ? bB : bA;
        const float* M = pass ? MB : MA;
        const int qtok = (pass ? sB : sA)[L_ - 1];
        float ctx;
        {
            float qv[H_];
            const float4* kp = (const float4*)(tsh + qtok * H_);
#pragma unroll
            for (int q = 0; q < 8; q++) {
                float4 f = kp[q];
                qv[4*q+0] = f.x; qv[4*q+1] = f.y; qv[4*q+2] = f.z; qv[4*q+3] = f.w;
            }
            ctx = neon_dot32(M, qv);
        }

        scratch[lane] = ctx;
        __syncwarp();
        float r = 0.0f;
#pragma unroll
        for (int j = 0; j < H_; j++) r = fmaf(scratch[j], w_read[j * H_ + lane], r);
        r = __fadd_rn(r, b_read[lane]);
        __syncwarp();
        scratch[lane] = r;
        __syncwarp();

        float o0 = 0.0f, o1 = 0.0f;
#pragma unroll
        for (int j = 0; j < H_; j++) {
            const float rj = scratch[j];
            o0 = fmaf(rj, w_out[j * V_ + lane], o0);
            o1 = fmaf(rj, w_out[j * V_ + lane + H_], o1);
        }
        out[b * V_ + lane]      = __fadd_rn(o0, b_out[lane]);
        out[b * V_ + lane + H_] = __fadd_rn(o1, b_out[lane + H_]);
        __syncwarp();
    }

    if (lane == 0) atomicAdd(&g_writes, writes);
}

// ---------------------------------------------------------------------------
__global__ void finalize_kernel(float* __restrict__ out, int out_size)
{
    if (out_size > B_ * V_)
        out[B_ * V_] = __fdiv_rn((float)g_writes, (float)(STEPS * B_));
}

extern "C" void kernel_launch(void* const* d_in, const int* in_sizes, int n_in,
                              void* d_out, int out_size)
{
    const int*   seq    = (const int*)d_in[0];
    const float* embed  = (const float*)d_in[1];
    const float* w1     = (const float*)d_in[2];
    const float* b1     = (const float*)d_in[3];
    const float* w2     = (const float*)d_in[4];
    const float* b2     = (const float*)d_in[5];
    const float* ln_g   = (const float*)d_in[6];
    const float* ln_b   = (const float*)d_in[7];
    const float* w_read = (const float*)d_in[8];
    const float* b_read = (const float*)d_in[9];
    const float* w_out  = (const float*)d_in[10];
    const float* b_out  = (const float*)d_in[11];
    float* out = (float*)d_out;

    precompute_kernel<<<V_, 64>>>(embed, w1, b1, w2, b2, ln_g, ln_b);
    scan_kernel<<<B_ / 2, 32>>>(seq, w_read, b_read, w_out, b_out, out);
    finalize_kernel<<<1, 1>>>(out, out_size);
}

// round 9
// speedup vs baseline: 1.3866x; 1.3866x over previous
#include <cuda_runtime.h>

// EnergyGatedDeltaModel — GB300 sm_103a
// R8 = R6/R7 arithmetic (bit-identical decisions) + pairable slow path:
//  - cache the 16 NEON chain accumulators of ||M||^2 per batch (aold, lanes 0-15);
//    valid unless invalidated by a fast-path accept. Slow step w/ valid cache
//    needs only the Mn chain (16 lanes) -> two batches' slow paths run in
//    parallel across half-warps (the R7 serialization bug).
//  - kv read directly from shared (register pressure down), padded-row (36)
//    slow-path buffers (conflict-free STS128 + chain LDS).
//  - precompute: 64x64 phase-parallel (R7, 7us).

#define B_ 512
#define L_ 2048
#define H_ 32
#define V_ 64
#define STEPS (L_ - 1)
#define THRESH 1.0f
#define ROWP 36   // padded row stride for slow-path buffers

__device__ float g_table[V_ * H_];
__device__ float g_ksq[V_];
__device__ float g_denom[V_];
__device__ int   g_writes;

// NEON VF4xIC4 reduction of 32 products (R6-identical values).
__device__ __forceinline__ float neon_dot32(const float* x, const float* y) {
    float A[16];
#pragma unroll
    for (int c = 0; c < 16; c++) A[c] = __fmul_rn(x[c], y[c]);
#pragma unroll
    for (int c = 0; c < 16; c++) A[c] = fmaf(x[16 + c], y[16 + c], A[c]);
    float V[4];
#pragma unroll
    for (int l = 0; l < 4; l++)
        V[l] = __fadd_rn(__fadd_rn(__fadd_rn(A[l], A[4 + l]), A[8 + l]), A[12 + l]);
    return __fadd_rn(__fadd_rn(V[0], V[2]), __fadd_rn(V[1], V[3]));
}

__device__ __forceinline__ float neon_sum32(const float* t) {
    float A[16];
#pragma unroll
    for (int c = 0; c < 16; c++) A[c] = __fadd_rn(t[c], t[16 + c]);
    float V[4];
#pragma unroll
    for (int l = 0; l < 4; l++)
        V[l] = __fadd_rn(__fadd_rn(__fadd_rn(A[l], A[4 + l]), A[8 + l]), A[12 + l]);
    return __fadd_rn(__fadd_rn(V[0], V[2]), __fadd_rn(V[1], V[3]));
}

// ---------------------------------------------------------------------------
__global__ void precompute_kernel(const float* __restrict__ embed,
                                  const float* __restrict__ w1,
                                  const float* __restrict__ b1,
                                  const float* __restrict__ w2,
                                  const float* __restrict__ b2,
                                  const float* __restrict__ ln_g,
                                  const float* __restrict__ ln_b)
{
    __shared__ float h_sh[H_];
    __shared__ float s_sh[2 * H_];
    __shared__ float x_sh[H_];

    const int v = blockIdx.x;
    const int t = threadIdx.x;
    if (v == 0 && t == 0) g_writes = 0;

    if (t < H_) h_sh[t] = embed[v * H_ + t];
    __syncthreads();

    {   // phase 1: s_j
        const int j = t;
        float s = 0.0f;
#pragma unroll
        for (int i = 0; i < H_; i++) s = fmaf(h_sh[i], w1[i * 2 * H_ + j], s);
        s = __fadd_rn(s, b1[j]);
        s_sh[j] = fmaxf(s, 0.0f);
    }
    __syncthreads();

    if (t < H_) {   // phase 2: x_i
        const int i = t;
        float acc = 0.0f;
#pragma unroll
        for (int j = 0; j < 2 * H_; j++) acc = fmaf(s_sh[j], w2[j * H_ + i], acc);
        float ff = __fadd_rn(acc, b2[i]);
        x_sh[i] = __fadd_rn(h_sh[i], ff);
    }
    __syncthreads();

    if (t == 0) {   // phase 3: LN + ksq (R6-identical order)
        float x[H_], d[H_], sq[H_];
#pragma unroll
        for (int i = 0; i < H_; i++) x[i] = x_sh[i];
        float mu = __fmul_rn(neon_sum32(x), 1.0f / H_);
#pragma unroll
        for (int i = 0; i < H_; i++) {
            d[i] = __fsub_rn(x[i], mu);
            sq[i] = __fmul_rn(d[i], d[i]);
        }
        float var = __fmul_rn(neon_sum32(sq), 1.0f / H_);
        float rs = __fdiv_rn(1.0f, __fsqrt_rn(__fadd_rn(var, 1e-5f)));
        float y[H_];
#pragma unroll
        for (int i = 0; i < H_; i++) {
            y[i] = __fadd_rn(__fmul_rn(__fmul_rn(d[i], rs), ln_g[i]), ln_b[i]);
            g_table[v * H_ + i] = y[i];
            sq[i] = __fmul_rn(y[i], y[i]);
        }
        float ksq = neon_sum32(sq);
        g_ksq[v]   = ksq;
        g_denom[v] = __fadd_rn(ksq, 1e-6f);
    }
}

// ---------------------------------------------------------------------------
// Slow-path helpers (values identical to R6's exact gate).
// ---------------------------------------------------------------------------

// 64-step fma chain for accumulator c over padded-row buffer (rows of 32, pad 36).
__device__ __forceinline__ float chain64(const float* P, int c) {
    float a = 0.0f;
#pragma unroll
    for (int m = 0; m < 64; m++) {
        float s = P[(m >> 1) * ROWP + (m & 1) * 16 + c];
        a = fmaf(s, s, a);
    }
    return a;
}

// NEON fold of 16 per-chain accumulators living in lanes base..base+15.
__device__ __forceinline__ float fold16(float val, int base, unsigned FULL) {
    float V[4];
#pragma unroll
    for (int l = 0; l < 4; l++) {
        float a0 = __shfl_sync(FULL, val, base + l);
        float a1 = __shfl_sync(FULL, val, base + l + 4);
        float a2 = __shfl_sync(FULL, val, base + l + 8);
        float a3 = __shfl_sync(FULL, val, base + l + 12);
        V[l] = __fadd_rn(__fadd_rn(__fadd_rn(a0, a1), a2), a3);
    }
    return __fadd_rn(__fadd_rn(V[0], V[2]), __fadd_rn(V[1], V[3]));
}

__device__ __forceinline__ void store_row(float* buf, int lane, const float* Mrow) {
    float4* p = (float4*)(buf + lane * ROWP);
#pragma unroll
    for (int q = 0; q < 8; q++)
        p[q] = make_float4(Mrow[4*q], Mrow[4*q+1], Mrow[4*q+2], Mrow[4*q+3]);
}

__device__ __forceinline__ void store_row_mn(float* buf, int lane, const float* Mrow,
                                             float u, const float* k) {
    float4* p = (float4*)(buf + lane * ROWP);
#pragma unroll
    for (int q = 0; q < 8; q++)
        p[q] = make_float4(fmaf(u, k[4*q],   Mrow[4*q]),
                           fmaf(u, k[4*q+1], Mrow[4*q+1]),
                           fmaf(u, k[4*q+2], Mrow[4*q+2]),
                           fmaf(u, k[4*q+3], Mrow[4*q+3]));
    }

// Single-batch exact gate with aold cache (warp-uniform valid flag).
__device__ __forceinline__ int resolve_single(const float* M, float u, const float* k,
                                              float& aold, bool& valid,
                                              float* mnbuf, float* mobuf,
                                              int lane, unsigned FULL)
{
    int g;
    if (valid) {
        store_row_mn(mnbuf, lane, M, u, k);
        __syncwarp();
        float a = 0.0f;
        if (lane < 16) a = chain64(mnbuf, lane);
        __syncwarp();
        float en = fold16(a, 0, FULL);
        float eo = fold16(aold, 0, FULL);
        g = en > eo;
        if (g && lane < 16) aold = a;
    } else {
        store_row(mobuf, lane, M);
        store_row_mn(mnbuf, lane, M, u, k);
        __syncwarp();
        float a = chain64((lane < 16) ? mobuf : mnbuf, lane & 15);
        __syncwarp();
        float eo = fold16(a, 0, FULL);
        float en = fold16(a, 16, FULL);
        float anew = __shfl_sync(FULL, a, (lane & 15) + 16);
        g = en > eo;
        if (lane < 16) aold = g ? anew : a;
        valid = true;
    }
    return g;
}

// ---------------------------------------------------------------------------
// Scan: one warp handles two batches; slow paths pair across half-warps.
// ---------------------------------------------------------------------------
__global__ void __launch_bounds__(32) scan_kernel(const int* __restrict__ seq,
                                                  const float* __restrict__ w_read,
                                                  const float* __restrict__ b_read,
                                                  const float* __restrict__ w_out,
                                                  const float* __restrict__ b_out,
                                                  float* __restrict__ out)
{
    __shared__ __align__(16) float tsh[V_ * H_];
    __shared__ __align__(16) float mnA[H_ * ROWP];
    __shared__ __align__(16) float mnB[H_ * ROWP];
    __shared__ __align__(16) float mo[H_ * ROWP];
    __shared__ float dnsh[V_];
    __shared__ float kssh[V_];
    __shared__ int   toksA[32];
    __shared__ int   toksB[32];
    __shared__ float scratch[H_];

    const int lane = threadIdx.x;
    const int bA   = blockIdx.x;
    const int bB   = blockIdx.x + 256;
    const unsigned FULL = 0xffffffffu;

    for (int i = lane; i < V_ * H_; i += 32) tsh[i] = g_table[i];
    dnsh[lane]      = g_denom[lane];
    dnsh[lane + 32] = g_denom[lane + 32];
    kssh[lane]      = g_ksq[lane];
    kssh[lane + 32] = g_ksq[lane + 32];
    __syncwarp();

    float MA[H_], MB[H_];
#pragma unroll
    for (int j = 0; j < H_; j++) { MA[j] = 0.0f; MB[j] = 0.0f; }

    float aoldA = 0.0f, aoldB = 0.0f;   // ||M||^2 chain accumulators (lanes 0-15)
    bool validA = true, validB = true;  // M=0 -> chains are exactly 0

    int writes = 0;
    const int* sA = seq + bA * L_;
    const int* sB = seq + bB * L_;

    for (int t0 = 0; t0 < STEPS; t0 += 32) {
        toksA[lane] = sA[t0 + lane];
        toksB[lane] = sB[t0 + lane];
        __syncwarp();
        const int tend = (STEPS - t0) < 32 ? (STEPS - t0) : 32;

        for (int tt = 0; tt < tend; tt++) {
            const float* kA = tsh + toksA[tt] * H_;
            const float* kB = tsh + toksB[tt] * H_;
            const float dnA = dnsh[toksA[tt]], ksA = kssh[toksA[tt]];
            const float dnB = dnsh[toksB[tt]], ksB = kssh[toksB[tt]];

            const float vA = neon_dot32(MA, kA);
            const float vB = neon_dot32(MB, kB);

            const float uA = __fsub_rn(kA[lane], __fdiv_rn(vA, dnA));
            const float uB = __fsub_rn(kB[lane], __fdiv_rn(vB, dnB));

            float suvA = __fmul_rn(uA, vA);
            float suuA = __fmul_rn(uA, uA);
            float suvB = __fmul_rn(uB, vB);
            float suuB = __fmul_rn(uB, uB);
#pragma unroll
            for (int o = 16; o > 0; o >>= 1) {
                suvA += __shfl_xor_sync(FULL, suvA, o);
                suuA += __shfl_xor_sync(FULL, suuA, o);
                suvB += __shfl_xor_sync(FULL, suvB, o);
                suuB += __shfl_xor_sync(FULL, suuB, o);
            }
            const float dEA = __fadd_rn(__fadd_rn(suvA, suvA), __fmul_rn(suuA, ksA));
            const float dEB = __fadd_rn(__fadd_rn(suvB, suvB), __fmul_rn(suuB, ksB));

            const bool slowA = fabsf(dEA) < THRESH;
            const bool slowB = fabsf(dEB) < THRESH;
            int gateA = dEA > 0.0f;
            int gateB = dEB > 0.0f;

            if (slowA | slowB) {
                if (slowA & slowB & validA & validB) {
                    // paired: A's Mn chain on lanes 0-15, B's on 16-31
                    store_row_mn(mnA, lane, MA, uA, kA);
                    store_row_mn(mnB, lane, MB, uB, kB);
                    __syncwarp();
                    float a = chain64((lane < 16) ? mnA : mnB, lane & 15);
                    __syncwarp();
                    float enA = fold16(a, 0, FULL);
                    float enB = fold16(a, 16, FULL);
                    float eoA = fold16(aoldA, 0, FULL);
                    float eoB = fold16(aoldB, 0, FULL);
                    gateA = enA > eoA;
                    gateB = enB > eoB;
                    float aB = __shfl_sync(FULL, a, (lane & 15) + 16);
                    if (lane < 16) {
                        if (gateA) aoldA = a;
                        if (gateB) aoldB = aB;
                    }
                } else {
                    if (slowA)
                        gateA = resolve_single(MA, uA, kA, aoldA, validA, mnA, mo, lane, FULL);
                    if (slowB)
                        gateB = resolve_single(MB, uB, kB, aoldB, validB, mnB, mo, lane, FULL);
                }
            }

            if (gateA) {
                writes++;
#pragma unroll
                for (int j = 0; j < H_; j++) MA[j] = fmaf(uA, kA[j], MA[j]);
                if (!slowA) validA = false;
            }
            if (gateB) {
                writes++;
#pragma unroll
                for (int j = 0; j < H_; j++) MB[j] = fmaf(uB, kB[j], MB[j]);
                if (!slowB) validB = false;
            }
        }
        __syncwarp();
    }

    // -------- readout (both batches), identical arithmetic --------
#pragma unroll
    for (int pass = 0; pass < 2; pass++) {
        const int b = pass ? bB : bA;
        const float* M = pass ? MB : MA;
        const int qtok = (pass ? sB : sA)[L_ - 1];
        const float* qv = tsh + qtok * H_;
        float ctx = neon_dot32(M, qv);

        scratch[lane] = ctx;
        __syncwarp();
        float r = 0.0f;
#pragma unroll
        for (int j = 0; j < H_; j++) r = fmaf(scratch[j], w_read[j * H_ + lane], r);
        r = __fadd_rn(r, b_read[lane]);
        __syncwarp();
        scratch[lane] = r;
        __syncwarp();

        float o0 = 0.0f, o1 = 0.0f;
#pragma unroll
        for (int j = 0; j < H_; j++) {
            const float rj = scratch[j];
            o0 = fmaf(rj, w_out[j * V_ + lane], o0);
            o1 = fmaf(rj, w_out[j * V_ + lane + H_], o1);
        }
        out[b * V_ + lane]      = __fadd_rn(o0, b_out[lane]);
        out[b * V_ + lane + H_] = __fadd_rn(o1, b_out[lane + H_]);
        __syncwarp();
    }

    if (lane == 0) atomicAdd(&g_writes, writes);
}

// ---------------------------------------------------------------------------
__global__ void finalize_kernel(float* __restrict__ out, int out_size)
{
    if (out_size > B_ * V_)
        out[B_ * V_] = __fdiv_rn((float)g_writes, (float)(STEPS * B_));
}

extern "C" void kernel_launch(void* const* d_in, const int* in_sizes, int n_in,
                              void* d_out, int out_size)
{
    const int*   seq    = (const int*)d_in[0];
    const float* embed  = (const float*)d_in[1];
    const float* w1     = (const float*)d_in[2];
    const float* b1     = (const float*)d_in[3];
    const float* w2     = (const float*)d_in[4];
    const float* b2     = (const float*)d_in[5];
    const float* ln_g   = (const float*)d_in[6];
    const float* ln_b   = (const float*)d_in[7];
    const float* w_read = (const float*)d_in[8];
    const float* b_read = (const float*)d_in[9];
    const float* w_out  = (const float*)d_in[10];
    const float* b_out  = (const float*)d_in[11];
    float* out = (float*)d_out;

    precompute_kernel<<<V_, 64>>>(embed, w1, b1, w2, b2, ln_g, ln_b);
    scan_kernel<<<B_ / 2, 32>>>(seq, w_read, b_read, w_out, b_out, out);
    finalize_kernel<<<1, 1>>>(out, out_size);
}